// round 5
// baseline (speedup 1.0000x reference)
#include <cuda_runtime.h>
#include <cstdint>
#include <math.h>

#define B_ 2048
#define S_ 100
#define POS_ 2
#define E_ 256
#define H_ 256
#define G4_ 1024

// libdevice precise exp/log — immune to --use_fast_math substitution
extern "C" __device__ float __nv_expf(float);
extern "C" __device__ float __nv_logf(float);

// ---------------- scratch (device globals; no allocations allowed) ----------------
__device__ __align__(256) float g_hA[B_ * H_];
__device__ __align__(256) float g_hB[B_ * H_];
__device__ __align__(256) float g_c[B_ * H_];
__device__ __align__(256) float g_enc_out[(size_t)B_ * S_ * H_];   // [b][s][h]
__device__ __align__(256) float g_k_ptr[(size_t)B_ * S_ * H_];
__device__ __align__(256) float g_k_gl[(size_t)B_ * S_ * H_];
__device__ __align__(256) float g_qg[B_ * H_];
__device__ __align__(256) float g_query[B_ * H_];
__device__ __align__(256) float g_qp[B_ * H_];
__device__ __align__(256) float g_Whh1[G4_ * H_];   // gate-interleaved encoder Whh
__device__ __align__(256) float g_Whh2[G4_ * H_];   // gate-interleaved decoder Whh
__device__ __align__(256) float g_Wk[(H_ * 2) * H_]; // packed [ptr_Wk ; gl_Wk]
__device__ __align__(256) float g_kb[H_ * 2];        // packed [ptr_bk ; gl_bk]
__device__ unsigned char g_mask[B_ * S_];
__device__ int g_chosen[B_];
__device__ float g_M1[G4_ * 2];
__device__ float g_beta1[G4_];
__device__ float g_M2[G4_ * 2];
__device__ float g_beta2[G4_];
__device__ float g_sosx[G4_];

// ---------------- XLA-exact tanh (EmitTanh f32) ----------------
__device__ __forceinline__ float tanh_xla(float x) {
    float ax = fabsf(x);
    float xc = fminf(fmaxf(x, -7.90531110763549805f), 7.90531110763549805f);
    float x2 = xc * xc;
    float p = -2.76076847742355e-16f;
    p = p * x2 + 2.00018790482477e-13f;
    p = p * x2 + -8.60467152213735e-11f;
    p = p * x2 + 5.12229709037114e-07f;
    p = p * x2 + 1.48572235717979e-05f;
    p = p * x2 + 6.37261928875436e-04f;
    p = p * x2 + 4.89352455891786e-03f;
    p = p * xc;
    float q = 1.19825839466702e-06f;
    q = q * x2 + 1.18534705686654e-04f;
    q = q * x2 + 2.26843463243900e-03f;
    q = q * x2 + 4.89352518554385e-03f;
    float r = __fdiv_rn(p, q);
    return (ax < 0.0004f) ? x : r;
}
// Fast variant for the attention inner loop: same P/Q, reciprocal via
// rcp.approx + 1 Newton (rel err ~1e-7, below GEMM reduction-order noise).
__device__ __forceinline__ float tanh_fast(float x) {
    float ax = fabsf(x);
    float xc = fminf(fmaxf(x, -7.90531110763549805f), 7.90531110763549805f);
    float x2 = xc * xc;
    float p = -2.76076847742355e-16f;
    p = p * x2 + 2.00018790482477e-13f;
    p = p * x2 + -8.60467152213735e-11f;
    p = p * x2 + 5.12229709037114e-07f;
    p = p * x2 + 1.48572235717979e-05f;
    p = p * x2 + 6.37261928875436e-04f;
    p = p * x2 + 4.89352455891786e-03f;
    p = p * xc;
    float q = 1.19825839466702e-06f;
    q = q * x2 + 1.18534705686654e-04f;
    q = q * x2 + 2.26843463243900e-03f;
    q = q * x2 + 4.89352518554385e-03f;
    float r;
    asm("rcp.approx.f32 %0, %1;" : "=f"(r) : "f"(q));
    r = r * (2.0f - q * r);          // 1 Newton iteration
    float t = p * r;
    return (ax < 0.0004f) ? x : t;
}
// XLA LogisticExpander: logistic(x) = 0.5 + 0.5 * tanh(0.5 * x)
__device__ __forceinline__ float sigmoid_xla(float x) {
    return 0.5f + 0.5f * tanh_xla(0.5f * x);
}

// ---------------- threefry2x32 (JAX-exact) ----------------
#define TF_ROT(x1v, r) ((x1v << r) | (x1v >> (32 - r)))
__host__ __device__ inline void threefry2x32(unsigned k0, unsigned k1,
                                             unsigned c0, unsigned c1,
                                             unsigned& o0, unsigned& o1) {
    unsigned ks0 = k0, ks1 = k1, ks2 = k0 ^ k1 ^ 0x1BD11BDAu;
    unsigned x0 = c0 + ks0, x1 = c1 + ks1;
#define TF_R(r) { x0 += x1; x1 = TF_ROT(x1, r); x1 ^= x0; }
    TF_R(13) TF_R(15) TF_R(26) TF_R(6)   x0 += ks1; x1 += ks2 + 1u;
    TF_R(17) TF_R(29) TF_R(16) TF_R(24)  x0 += ks2; x1 += ks0 + 2u;
    TF_R(13) TF_R(15) TF_R(26) TF_R(6)   x0 += ks0; x1 += ks1 + 3u;
    TF_R(17) TF_R(29) TF_R(16) TF_R(24)  x0 += ks1; x1 += ks2 + 4u;
    TF_R(13) TF_R(15) TF_R(26) TF_R(6)   x0 += ks2; x1 += ks0 + 5u;
#undef TF_R
    o0 = x0; o1 = x1;
}

// ---------------- init ----------------
__global__ void init_kernel() {
    int i = blockIdx.x * blockDim.x + threadIdx.x;
    if (i < B_ * H_) { g_hA[i] = 0.f; g_hB[i] = 0.f; g_c[i] = 0.f; }
    if (i < B_ * S_) g_mask[i] = 0;
}

// ---------------- precompute: fold x-path (POS=2) into per-gate affine; interleave gates ----------------
// Original gate row r = gate*256 + h  ->  interleaved row n = h*4 + gate
__global__ void precompute_kernel(const float* __restrict__ emb_W, const float* __restrict__ emb_b,
                                  const float* __restrict__ enc_Wih, const float* __restrict__ enc_bih,
                                  const float* __restrict__ enc_bhh,
                                  const float* __restrict__ dec_Wih, const float* __restrict__ dec_bih,
                                  const float* __restrict__ dec_bhh,
                                  const float* __restrict__ dec_sos) {
    int r = blockIdx.x * blockDim.x + threadIdx.x;
    if (r >= G4_) return;
    int gate = r >> 8, h = r & 255;
    int n = (h << 2) | gate;
    float m10 = 0.f, m11 = 0.f, b1 = 0.f, m20 = 0.f, m21 = 0.f, b2 = 0.f, sx = 0.f;
    for (int e = 0; e < E_; e++) {
        float we0 = emb_W[e * 2 + 0], we1 = emb_W[e * 2 + 1], be = emb_b[e];
        float a = enc_Wih[r * E_ + e];
        float d = dec_Wih[r * E_ + e];
        m10 += a * we0; m11 += a * we1; b1 += a * be;
        m20 += d * we0; m21 += d * we1; b2 += d * be;
        sx += d * dec_sos[e];
    }
    g_M1[n * 2] = m10; g_M1[n * 2 + 1] = m11; g_beta1[n] = b1 + enc_bih[r] + enc_bhh[r];
    g_M2[n * 2] = m20; g_M2[n * 2 + 1] = m21; g_beta2[n] = b2 + dec_bih[r] + dec_bhh[r];
    g_sosx[n] = sx + dec_bih[r] + dec_bhh[r];
}

// reorder Whh to gate-interleaved; pack [ptr_Wk ; gl_Wk] and biases
__global__ void pack_weights_kernel(const float* __restrict__ enc_Whh,
                                    const float* __restrict__ dec_Whh,
                                    const float* __restrict__ ptr_Wk,
                                    const float* __restrict__ gl_Wk,
                                    const float* __restrict__ ptr_bk,
                                    const float* __restrict__ gl_bk) {
    int idx = blockIdx.x * blockDim.x + threadIdx.x;   // over 1024*256
    int r = idx >> 8, k = idx & 255;
    int gate = r >> 8, h = r & 255;
    int n = (h << 2) | gate;
    g_Whh1[n * H_ + k] = enc_Whh[idx];
    g_Whh2[n * H_ + k] = dec_Whh[idx];
    if (idx < 2 * H_ * H_) {
        g_Wk[idx] = (idx < H_ * H_) ? ptr_Wk[idx] : gl_Wk[idx - H_ * H_];
    }
    if (idx < 2 * H_) {
        g_kb[idx] = (idx < H_) ? ptr_bk[idx] : gl_bk[idx - H_];
    }
}

// ---------------- plain GEMM: C[M,N] = A[M,K]*B[N,K]^T + bias[n] ----------------
// SPLIT_COL >= 0: columns [0,SPLIT_COL) go to Cm, columns >= SPLIT_COL go to C2 (col-SPLIT_COL)
template <int BM, int BN, int BK, int TM, int TN, int SPLIT_COL>
__global__ __launch_bounds__(256) void gemm_bias_kernel(
        const float* __restrict__ A, const float* __restrict__ Bm,
        float* __restrict__ Cm, float* __restrict__ C2,
        int M, int N, int K, const float* __restrict__ bias) {
    constexpr int TX = BN / TN, TY = BM / TM, NT = TX * TY;
    __shared__ float sA[BK][BM];
    __shared__ float sB[BK][BN];
    int tid = threadIdx.x;
    int tx = tid % TX, ty = tid / TX;
    int bm0 = blockIdx.x * BM, bn0 = blockIdx.y * BN;
    float acc[TM][TN];
#pragma unroll
    for (int i = 0; i < TM; i++)
#pragma unroll
        for (int j = 0; j < TN; j++) acc[i][j] = 0.f;
    constexpr int LA = (BM * BK / 4) / NT;
    constexpr int LB = (BN * BK / 4) / NT;
    for (int kt = 0; kt < K; kt += BK) {
#pragma unroll
        for (int l = 0; l < LA; l++) {
            int idx = tid + l * NT;
            int r = idx / (BK / 4), c4 = idx % (BK / 4);
            float4 v = *reinterpret_cast<const float4*>(&A[(size_t)(bm0 + r) * K + kt + c4 * 4]);
            sA[c4 * 4 + 0][r] = v.x; sA[c4 * 4 + 1][r] = v.y;
            sA[c4 * 4 + 2][r] = v.z; sA[c4 * 4 + 3][r] = v.w;
        }
#pragma unroll
        for (int l = 0; l < LB; l++) {
            int idx = tid + l * NT;
            int r = idx / (BK / 4), c4 = idx % (BK / 4);
            float4 v = *reinterpret_cast<const float4*>(&Bm[(size_t)(bn0 + r) * K + kt + c4 * 4]);
            sB[c4 * 4 + 0][r] = v.x; sB[c4 * 4 + 1][r] = v.y;
            sB[c4 * 4 + 2][r] = v.z; sB[c4 * 4 + 3][r] = v.w;
        }
        __syncthreads();
#pragma unroll
        for (int kk = 0; kk < BK; kk++) {
            float ra[TM], rb[TN];
#pragma unroll
            for (int i = 0; i < TM; i++) ra[i] = sA[kk][ty * TM + i];
#pragma unroll
            for (int j = 0; j < TN; j++) rb[j] = sB[kk][tx * TN + j];
#pragma unroll
            for (int i = 0; i < TM; i++)
#pragma unroll
                for (int j = 0; j < TN; j++) acc[i][j] += ra[i] * rb[j];
        }
        __syncthreads();
    }
#pragma unroll
    for (int i = 0; i < TM; i++) {
        int row = bm0 + ty * TM + i;
#pragma unroll
        for (int j = 0; j < TN; j++) {
            int col = bn0 + tx * TN + j;
            float v = acc[i][j] + bias[col];
            if (SPLIT_COL < 0 || col < SPLIT_COL)
                Cm[(size_t)row * (SPLIT_COL < 0 ? N : SPLIT_COL) + col] = v;
            else
                C2[(size_t)row * (N - SPLIT_COL) + (col - SPLIT_COL)] = v;
        }
    }
}

// ---------------- fused gates-GEMM + LSTM cell ----------------
// A = h_in [B,256], Bm = gate-interleaved Whh [1024,256].
// Columns n = h*4 + {i,f,g,o}; each epilogue thread owns 8 consecutive columns = 2 h units.
// MODE 1: encoder (x-term from inputs[row,t], store enc_out)
// MODE 2: decoder (t==0 -> sosx; else x-term from inputs[row,chosen[row]])
template <int MODE>
__global__ __launch_bounds__(256) void gemm_lstm_kernel(
        const float* __restrict__ h_in, const float* __restrict__ Bm,
        float* __restrict__ c_st, float* __restrict__ h_out,
        float* __restrict__ enc_out,
        const float* __restrict__ inputs, const int* __restrict__ chosen,
        const float* __restrict__ Mr, const float* __restrict__ betar,
        const float* __restrict__ sosxr, int t) {
    constexpr int BM = 128, BN = 128, BK = 16, TM = 8, TN = 8;
    constexpr int TX = BN / TN, TY = BM / TM, NT = TX * TY;
    __shared__ float sA[BK][BM];
    __shared__ float sB[BK][BN];
    int tid = threadIdx.x;
    int tx = tid % TX, ty = tid / TX;
    int bm0 = blockIdx.x * BM, bn0 = blockIdx.y * BN;
    float acc[TM][TN];
#pragma unroll
    for (int i = 0; i < TM; i++)
#pragma unroll
        for (int j = 0; j < TN; j++) acc[i][j] = 0.f;
    constexpr int LA = (BM * BK / 4) / NT;
    constexpr int LB = (BN * BK / 4) / NT;
    for (int kt = 0; kt < H_; kt += BK) {
#pragma unroll
        for (int l = 0; l < LA; l++) {
            int idx = tid + l * NT;
            int r = idx / (BK / 4), c4 = idx % (BK / 4);
            float4 v = *reinterpret_cast<const float4*>(&h_in[(size_t)(bm0 + r) * H_ + kt + c4 * 4]);
            sA[c4 * 4 + 0][r] = v.x; sA[c4 * 4 + 1][r] = v.y;
            sA[c4 * 4 + 2][r] = v.z; sA[c4 * 4 + 3][r] = v.w;
        }
#pragma unroll
        for (int l = 0; l < LB; l++) {
            int idx = tid + l * NT;
            int r = idx / (BK / 4), c4 = idx % (BK / 4);
            float4 v = *reinterpret_cast<const float4*>(&Bm[(size_t)(bn0 + r) * H_ + kt + c4 * 4]);
            sB[c4 * 4 + 0][r] = v.x; sB[c4 * 4 + 1][r] = v.y;
            sB[c4 * 4 + 2][r] = v.z; sB[c4 * 4 + 3][r] = v.w;
        }
        __syncthreads();
#pragma unroll
        for (int kk = 0; kk < BK; kk++) {
            float ra[TM], rb[TN];
#pragma unroll
            for (int i = 0; i < TM; i++) ra[i] = sA[kk][ty * TM + i];
#pragma unroll
            for (int j = 0; j < TN; j++) rb[j] = sB[kk][tx * TN + j];
#pragma unroll
            for (int i = 0; i < TM; i++)
#pragma unroll
                for (int j = 0; j < TN; j++) acc[i][j] += ra[i] * rb[j];
        }
        __syncthreads();
    }
    int col0 = bn0 + tx * TN;           // multiple of 8
    int h0 = col0 >> 2;                 // two h units: h0, h0+1
#pragma unroll
    for (int i = 0; i < TM; i++) {
        int row = bm0 + ty * TM + i;
        float in0 = 0.f, in1 = 0.f;
        bool use_x = true;
        if (MODE == 1) {
            in0 = inputs[((size_t)row * S_ + t) * 2 + 0];
            in1 = inputs[((size_t)row * S_ + t) * 2 + 1];
        } else {
            if (t == 0) use_x = false;
            else {
                int s = chosen[row];
                in0 = inputs[((size_t)row * S_ + s) * 2 + 0];
                in1 = inputs[((size_t)row * S_ + s) * 2 + 1];
            }
        }
        float gv[8];
#pragma unroll
        for (int j = 0; j < TN; j++) {
            int col = col0 + j;
            float v = acc[i][j];
            if (use_x) v += in0 * Mr[col * 2] + in1 * Mr[col * 2 + 1] + betar[col];
            else       v += sosxr[col];
            gv[j] = v;
        }
#pragma unroll
        for (int u = 0; u < 2; u++) {
            int h = h0 + u;
            float I = sigmoid_xla(gv[u * 4 + 0]);
            float F = sigmoid_xla(gv[u * 4 + 1]);
            float G = tanh_xla(gv[u * 4 + 2]);
            float O = sigmoid_xla(gv[u * 4 + 3]);
            size_t off = (size_t)row * H_ + h;
            float cn = F * c_st[off] + I * G;
            float hn = O * tanh_xla(cn);
            c_st[off] = cn;
            h_out[off] = hn;
            if (MODE == 1) enc_out[((size_t)row * S_ + t) * H_ + h] = hn;
        }
    }
}

// ---------------- glimpse attention: logits + softmax + readout, single DRAM pass ----------------
// Masked rows skipped entirely (no load, no tanh); k_sh zero-filled so readout stays NaN-free.
// dynamic smem: k tile [100][256] + q[256] + V[256] + p[128]
#define GL_SMEM ((S_ * H_ + H_ + H_ + 128) * 4)
__global__ __launch_bounds__(256) void glimpse_kernel(const float* __restrict__ V) {
    extern __shared__ float sm[];
    float* k_sh = sm;
    float* q_sh = sm + S_ * H_;
    float* V_sh = q_sh + H_;
    float* p_sh = V_sh + H_;
    int b = blockIdx.x;
    int tid = threadIdx.x;
    q_sh[tid] = g_qg[b * H_ + tid];
    V_sh[tid] = V[tid];
    __syncthreads();
    int warp = tid >> 5, lane = tid & 31;
    const float* kb = g_k_gl + (size_t)b * S_ * H_;
    for (int s = warp; s < S_; s += 8) {
        if (g_mask[b * S_ + s]) {
#pragma unroll
            for (int i = 0; i < 8; i++) k_sh[s * H_ + lane + i * 32] = 0.f;
            if (!lane) p_sh[s] = -INFINITY;
            continue;
        }
        const float* kr = kb + s * H_;
        float accv = 0.f;
#pragma unroll
        for (int i = 0; i < 8; i++) {
            int h = lane + i * 32;
            float kv = kr[h];
            k_sh[s * H_ + h] = kv;
            accv += tanh_fast(q_sh[h] + kv) * V_sh[h];
        }
#pragma unroll
        for (int o = 16; o; o >>= 1) accv += __shfl_down_sync(0xffffffffu, accv, o);
        if (!lane) p_sh[s] = 10.f * tanh_xla(accv);
    }
    __syncthreads();
    if (warp == 0) {
        float m = -INFINITY;
        for (int s = lane; s < S_; s += 32) m = fmaxf(m, p_sh[s]);
#pragma unroll
        for (int o = 16; o; o >>= 1) m = fmaxf(m, __shfl_xor_sync(0xffffffffu, m, o));
        float d = 0.f;
        float ev[4];
#pragma unroll
        for (int i = 0; i < 4; i++) {
            int s = lane + i * 32;
            ev[i] = (s < S_) ? __nv_expf(p_sh[s] - m) : 0.f;
            d += ev[i];
        }
#pragma unroll
        for (int o = 16; o; o >>= 1) d += __shfl_xor_sync(0xffffffffu, d, o);
#pragma unroll
        for (int i = 0; i < 4; i++) {
            int s = lane + i * 32;
            if (s < S_) p_sh[s] = __fdiv_rn(ev[i], d);   // XLA softmax divides per element
        }
    }
    __syncthreads();
    float accv = 0.f;
#pragma unroll 4
    for (int s = 0; s < S_; s++) accv += p_sh[s] * k_sh[s * H_ + tid];
    g_query[b * H_ + tid] = accv;
}

// ---------------- pointer attention + gumbel-max sampling ----------------
__global__ __launch_bounds__(256) void pointer_kernel(const float* __restrict__ V,
                                                      float* __restrict__ out,
                                                      int t, unsigned k1, unsigned k2, int out_size) {
    int b = blockIdx.x;
    int tid = threadIdx.x;
    __shared__ float q_sh[H_], V_sh[H_], lp_sh[S_], y_sh[S_];
    q_sh[tid] = g_qp[b * H_ + tid];
    V_sh[tid] = V[tid];
    __syncthreads();
    int warp = tid >> 5, lane = tid & 31;
    const float* kb = g_k_ptr + (size_t)b * S_ * H_;
    for (int s = warp; s < S_; s += 8) {
        if (g_mask[b * S_ + s]) {
            if (!lane) lp_sh[s] = -INFINITY;
            continue;
        }
        const float* kr = kb + s * H_;
        float accv = 0.f;
#pragma unroll
        for (int i = 0; i < 8; i++) {
            int h = lane + i * 32;
            accv += tanh_fast(q_sh[h] + kr[h]) * V_sh[h];
        }
#pragma unroll
        for (int o = 16; o; o >>= 1) accv += __shfl_down_sync(0xffffffffu, accv, o);
        if (!lane) lp_sh[s] = 10.f * tanh_xla(accv);
    }
    __syncthreads();
    float M = -INFINITY, D = 0.f;
    if (warp == 0) {
        for (int s = lane; s < S_; s += 32) M = fmaxf(M, lp_sh[s]);
#pragma unroll
        for (int o = 16; o; o >>= 1) M = fmaxf(M, __shfl_xor_sync(0xffffffffu, M, o));
        for (int s = lane; s < S_; s += 32) D += __nv_expf(lp_sh[s] - M);
#pragma unroll
        for (int o = 16; o; o >>= 1) D += __shfl_xor_sync(0xffffffffu, D, o);
    }
    // JAX partitionable threefry: bits = bits1 ^ bits2 over 64-bit iota n = b*S+s
    if (tid < S_) {
        unsigned o0, o1;
        threefry2x32(k1, k2, 0u, (unsigned)(b * S_ + tid), o0, o1);
        unsigned bits = o0 ^ o1;
        float f = __uint_as_float((bits >> 9) | 0x3f800000u) - 1.0f;
        float u = fmaxf(1.17549435e-38f, f);
        float gum = -__nv_logf(-__nv_logf(u));
        y_sh[tid] = lp_sh[tid] + gum;
    }
    __syncthreads();
    if (warp == 0) {
        float best = -INFINITY;
        int bi = S_;
        for (int s = lane; s < S_; s += 32) {
            float y = y_sh[s];
            if (y > best) { best = y; bi = s; }
        }
#pragma unroll
        for (int o = 16; o; o >>= 1) {
            float ob = __shfl_xor_sync(0xffffffffu, best, o);
            int oi = __shfl_xor_sync(0xffffffffu, bi, o);
            if (ob > best || (ob == best && oi < bi)) { best = ob; bi = oi; }
        }
        if (!lane) {
            int ch = bi;
            float logp = (lp_sh[ch] - M) - __nv_logf(D);
            out[(size_t)b * S_ + t] = logp;
            if (out_size >= 2 * B_ * S_)
                out[(size_t)B_ * S_ + (size_t)b * S_ + t] = (float)ch;
            g_chosen[b] = ch;
            g_mask[b * S_ + ch] = 1;
        }
    }
}

// ---------------- host orchestration ----------------
extern "C" void kernel_launch(void* const* d_in, const int* in_sizes, int n_in,
                              void* d_out, int out_size) {
    const float* inputs  = (const float*)d_in[0];
    const float* emb_W   = (const float*)d_in[1];
    const float* emb_b   = (const float*)d_in[2];
    const float* enc_Wih = (const float*)d_in[3];
    const float* enc_Whh = (const float*)d_in[4];
    const float* enc_bih = (const float*)d_in[5];
    const float* enc_bhh = (const float*)d_in[6];
    const float* dec_Wih = (const float*)d_in[7];
    const float* dec_Whh = (const float*)d_in[8];
    const float* dec_bih = (const float*)d_in[9];
    const float* dec_bhh = (const float*)d_in[10];
    const float* ptr_Wq  = (const float*)d_in[11];
    const float* ptr_bq  = (const float*)d_in[12];
    const float* ptr_Wk  = (const float*)d_in[13];
    const float* ptr_bk  = (const float*)d_in[14];
    const float* ptr_V   = (const float*)d_in[15];
    const float* gl_Wq   = (const float*)d_in[16];
    const float* gl_bq   = (const float*)d_in[17];
    const float* gl_Wk   = (const float*)d_in[18];
    const float* gl_bk   = (const float*)d_in[19];
    const float* gl_V    = (const float*)d_in[20];
    const float* dec_sos = (const float*)d_in[21];
    float* out = (float*)d_out;

    float *p_hA, *p_hB, *p_c, *p_enc, *p_kp, *p_kg, *p_query;
    float *p_M1, *p_b1, *p_M2, *p_b2, *p_sosx, *p_W1, *p_W2, *p_qg, *p_qp, *p_Wk, *p_kb;
    int* p_chosen;
    cudaGetSymbolAddress((void**)&p_hA, g_hA);
    cudaGetSymbolAddress((void**)&p_hB, g_hB);
    cudaGetSymbolAddress((void**)&p_c, g_c);
    cudaGetSymbolAddress((void**)&p_enc, g_enc_out);
    cudaGetSymbolAddress((void**)&p_kp, g_k_ptr);
    cudaGetSymbolAddress((void**)&p_kg, g_k_gl);
    cudaGetSymbolAddress((void**)&p_query, g_query);
    cudaGetSymbolAddress((void**)&p_M1, g_M1);
    cudaGetSymbolAddress((void**)&p_b1, g_beta1);
    cudaGetSymbolAddress((void**)&p_M2, g_M2);
    cudaGetSymbolAddress((void**)&p_b2, g_beta2);
    cudaGetSymbolAddress((void**)&p_sosx, g_sosx);
    cudaGetSymbolAddress((void**)&p_W1, g_Whh1);
    cudaGetSymbolAddress((void**)&p_W2, g_Whh2);
    cudaGetSymbolAddress((void**)&p_qg, g_qg);
    cudaGetSymbolAddress((void**)&p_qp, g_qp);
    cudaGetSymbolAddress((void**)&p_Wk, g_Wk);
    cudaGetSymbolAddress((void**)&p_kb, g_kb);
    cudaGetSymbolAddress((void**)&p_chosen, g_chosen);

    cudaFuncSetAttribute(glimpse_kernel, cudaFuncAttributeMaxDynamicSharedMemorySize, GL_SMEM);

    init_kernel<<<(B_ * H_ + 255) / 256, 256>>>();
    precompute_kernel<<<G4_ / 256, 256>>>(emb_W, emb_b, enc_Wih, enc_bih, enc_bhh,
                                          dec_Wih, dec_bih, dec_bhh, dec_sos);
    pack_weights_kernel<<<(G4_ * H_) / 256, 256>>>(enc_Whh, dec_Whh,
                                                   ptr_Wk, gl_Wk, ptr_bk, gl_bk);

    // encoder: 100 sequential fused GEMM+LSTM steps (h ping-pong)
    for (int t = 0; t < S_; t++) {
        const float* hin = (t & 1) ? p_hB : p_hA;
        float* hout = (t & 1) ? p_hA : p_hB;
        gemm_lstm_kernel<1><<<dim3(B_ / 128, G4_ / 128), 256>>>(
            hin, p_W1, p_c, hout, p_enc, inputs, nullptr, p_M1, p_b1, nullptr, t);
    }

    // both key projections in ONE GEMM (N=512, single read of enc_out):
    // cols [0,256) -> k_ptr, cols [256,512) -> k_gl
    gemm_bias_kernel<128, 128, 16, 8, 8, H_><<<dim3((B_ * S_) / 128, (2 * H_) / 128), 256>>>(
        p_enc, p_Wk, p_kp, p_kg, B_ * S_, 2 * H_, H_, p_kb);

    // decoder: 100 sequential steps
    for (int t = 0; t < S_; t++) {
        unsigned k1, k2;
        threefry2x32(0u, 42u, 0u, (unsigned)t, k1, k2);  // foldlike split of key(42)
        const float* hin = (t & 1) ? p_hB : p_hA;
        float* hout = (t & 1) ? p_hA : p_hB;
        gemm_lstm_kernel<2><<<dim3(B_ / 128, G4_ / 128), 256>>>(
            hin, p_W2, p_c, hout, nullptr, inputs, p_chosen, p_M2, p_b2, p_sosx, t);
        gemm_bias_kernel<64, 64, 16, 4, 4, -1><<<dim3(B_ / 64, H_ / 64), 256>>>(
            hout, gl_Wq, p_qg, nullptr, B_, H_, H_, gl_bq);
        glimpse_kernel<<<B_, 256, GL_SMEM>>>(gl_V);
        gemm_bias_kernel<64, 64, 16, 4, 4, -1><<<dim3(B_ / 64, H_ / 64), 256>>>(
            p_query, ptr_Wq, p_qp, nullptr, B_, H_, H_, ptr_bq);
        pointer_kernel<<<B_, 256>>>(ptr_V, out, t, k1, k2, out_size);
    }
}